// round 6
// baseline (speedup 1.0000x reference)
#include <cuda_runtime.h>
#include <cuda_bf16.h>
#include <math.h>
#include <stdint.h>

#define B_  512
#define S_  512
#define DI_ 256
#define DO_ 256

// Packed Wh A-fragments: [g(=t*8+chunk)][wm(8)][ks(4)][mt(2)][lane(32)], one float4 each.
// 4096 * 8 * 4 * 2 * 32 = 8,388,608 float4 = 134 MB.
__device__ float4 WhP_g[(size_t)S_ * 8 * 8 * 4 * 2 * 32];

// ---------------- helpers ----------------

__device__ __forceinline__ void cpasync16(void* smem_dst, const void* gsrc) {
    unsigned saddr = (unsigned)__cvta_generic_to_shared(smem_dst);
    asm volatile("cp.async.cg.shared.global [%0], [%1], 16;\n" :: "r"(saddr), "l"(gsrc));
}
__device__ __forceinline__ void cp_commit() { asm volatile("cp.async.commit_group;\n"); }
template <int N> __device__ __forceinline__ void cp_wait() {
    asm volatile("cp.async.wait_group %0;\n" :: "n"(N));
}
__device__ __forceinline__ unsigned f2u(float f) { return __float_as_uint(f); }
__device__ __forceinline__ float fast_tanh(float x) {
    float e = __expf(2.0f * x);
    return 1.0f - __fdividef(2.0f, e + 1.0f);
}
__device__ __forceinline__ uint32_t smem_u32(const void* p) {
    return (uint32_t)__cvta_generic_to_shared(p);
}

__device__ __forceinline__ void mma_tf32(float c[4],
                                         unsigned a0, unsigned a1, unsigned a2, unsigned a3,
                                         unsigned b0, unsigned b1) {
    asm volatile(
        "mma.sync.aligned.m16n8k8.row.col.f32.tf32.tf32.f32 "
        "{%0,%1,%2,%3}, {%4,%5,%6,%7}, {%8,%9}, {%0,%1,%2,%3};\n"
        : "+f"(c[0]), "+f"(c[1]), "+f"(c[2]), "+f"(c[3])
        : "r"(a0), "r"(a1), "r"(a2), "r"(a3), "r"(b0), "r"(b1));
}

#define LDSM_X4(r0, r1, r2, r3, addr) \
    asm volatile("ldmatrix.sync.aligned.m8n8.x4.shared.b16 {%0,%1,%2,%3}, [%4];" \
                 : "=r"(r0), "=r"(r1), "=r"(r2), "=r"(r3) : "r"(addr))

// ---------------- Phase 0: pack Wh into fragment-major layout (unchanged) ----------------

__global__ __launch_bounds__(256, 1) void prepack_wh(const float* __restrict__ Wh)
{
    __shared__ float tile[32 * 260];
    const int slab = blockIdx.x;
    const int t    = blockIdx.y;
    const int tid  = threadIdx.x;
    const float* src = Wh + (size_t)t * (DO_ * DO_) + (size_t)slab * 32 * DO_;

#pragma unroll
    for (int j = 0; j < 8; j++) {
        int idx = tid + j * 256;
        int r = idx >> 6, q = idx & 63;
        *(float4*)&tile[r * 260 + q * 4] = *(const float4*)&src[r * DO_ + q * 4];
    }
    __syncthreads();

    const size_t g = (size_t)t * 8 + slab;
#pragma unroll
    for (int j = 0; j < 8; j++) {
        int idx  = tid + j * 256;
        int lane = idx & 31;
        int mt   = (idx >> 5) & 1;
        int ks   = (idx >> 6) & 3;
        int wm   = (idx >> 8) & 7;
        int kloc = ks * 8 + (lane & 3);
        int m0   = wm * 32 + mt * 16 + (lane >> 2);
        float4 v;
        v.x = tile[kloc * 260 + m0];
        v.y = tile[kloc * 260 + m0 + 8];
        v.z = tile[(kloc + 4) * 260 + m0];
        v.w = tile[(kloc + 4) * 260 + m0 + 8];
        WhP_g[(g * 8 + wm) * 256 + (ks * 2 + mt) * 32 + lane] = v;
    }
}

// ---------------- Phase 1: Z[b,t,:] = x[b,t,:] @ Wx[t]  (unchanged, 2 CTAs/SM) ----------------

#define P1_AS  (128 * 36)
#define P1_BS  (32 * 132)
#define P1_SMEM ((2 * P1_AS + 2 * P1_BS) * 4)

__global__ __launch_bounds__(256, 2) void rnn_phase1(
    const float* __restrict__ x, const float* __restrict__ Wx, float* __restrict__ out)
{
    extern __shared__ float sm[];
    float* As[2] = { sm, sm + P1_AS };
    float* Bs[2] = { sm + 2 * P1_AS, sm + 2 * P1_AS + P1_BS };

    const int t      = blockIdx.z;
    const int m_base = blockIdx.y * 128;
    const int n_base = blockIdx.x * 128;
    const int tid    = threadIdx.x;
    const int warp   = tid >> 5, lane = tid & 31;
    const int wm     = warp & 3, wn = warp >> 2;
    const int grp    = lane >> 2, tig = lane & 3;

    float acc[2][8][4];
#pragma unroll
    for (int mt = 0; mt < 2; mt++)
#pragma unroll
        for (int nt = 0; nt < 8; nt++)
#pragma unroll
            for (int i = 0; i < 4; i++) acc[mt][nt][i] = 0.f;

    auto loadA = [&](int kc, int buf) {
#pragma unroll
        for (int j = 0; j < 4; j++) {
            int i = tid + j * 256;
            int r = i >> 3, q = i & 7;
            cpasync16(&As[buf][r * 36 + q * 4],
                      x + ((m_base + r) * S_ + t) * DI_ + kc * 32 + q * 4);
        }
        cp_commit();
    };
    auto loadB = [&](int kc, int buf) {
#pragma unroll
        for (int j = 0; j < 4; j++) {
            int i = tid + j * 256;
            int k = i >> 5, q = i & 31;
            cpasync16(&Bs[buf][k * 132 + q * 4],
                      Wx + t * (DI_ * DO_) + (kc * 32 + k) * DO_ + n_base + q * 4);
        }
        cp_commit();
    };

    loadA(0, 0); loadB(0, 0);
    loadA(1, 1); loadB(1, 1);

    for (int kc = 0; kc < 8; kc++) {
        if (kc < 7) cp_wait<2>(); else cp_wait<0>();
        __syncthreads();
        const int buf = kc & 1;
        const float* A = As[buf];
        const float* Bsm = Bs[buf];
#pragma unroll
        for (int ks = 0; ks < 4; ks++) {
            const int k = ks * 8;
            unsigned a[2][4];
#pragma unroll
            for (int mt = 0; mt < 2; mt++) {
                const int rb = wm * 32 + mt * 16;
                a[mt][0] = f2u(A[(rb + grp)     * 36 + k + tig]);
                a[mt][1] = f2u(A[(rb + grp + 8) * 36 + k + tig]);
                a[mt][2] = f2u(A[(rb + grp)     * 36 + k + 4 + tig]);
                a[mt][3] = f2u(A[(rb + grp + 8) * 36 + k + 4 + tig]);
            }
#pragma unroll
            for (int nt = 0; nt < 8; nt++) {
                const int cb = wn * 64 + nt * 8 + grp;
                unsigned b0 = f2u(Bsm[(k + tig)     * 132 + cb]);
                unsigned b1 = f2u(Bsm[(k + 4 + tig) * 132 + cb]);
#pragma unroll
                for (int mt = 0; mt < 2; mt++)
                    mma_tf32(acc[mt][nt], a[mt][0], a[mt][1], a[mt][2], a[mt][3], b0, b1);
            }
        }
        __syncthreads();
        if (kc + 2 < 8) { loadA(kc + 2, buf); loadB(kc + 2, buf); }
    }

#pragma unroll
    for (int mt = 0; mt < 2; mt++) {
#pragma unroll
        for (int nt = 0; nt < 8; nt++) {
            const int row = m_base + wm * 32 + mt * 16 + grp;
            const int col = n_base + wn * 64 + nt * 8 + 2 * tig;
            const int g0 = (row * S_ + t) * DO_ + col;
            float2 v0; v0.x = acc[mt][nt][0]; v0.y = acc[mt][nt][1];
            *(float2*)&out[g0] = v0;
            const int g1 = ((row + 8) * S_ + t) * DO_ + col;
            float2 v1; v1.x = acc[mt][nt][2]; v1.y = acc[mt][nt][3];
            *(float2*)&out[g1] = v1;
        }
    }
}

// ---------------- Phase 2 v4: 64 CTAs x 256 thr, no k-split, double-buffered h ----------------
// h_t^T = tanh(Z_t^T + Wh[t]^T @ h_{t-1}^T). 8 warps; warp w owns m cols [w*32, w*32+32),
// full K=256 (8 chunks of 32). A-frags: LDG.128 from WhP_g, 4-slot ring, distance-3 prefetch.
// B-frags: h via ldmatrix from double-buffered smem tile. One __syncthreads per step.

#define P2_HPAD 260

__global__ __launch_bounds__(256, 1) void rnn_phase2(float* __restrict__ out)
{
    __shared__ __align__(16) float hs[2][8 * P2_HPAD];

    const int tid  = threadIdx.x;
    const int w    = tid >> 5, lane = tid & 31;
    const int grp  = lane >> 2, tig = lane & 3;
    const int brow = blockIdx.x * 8;
    const int mb   = w * 32;
    const int n0   = 2 * tig;

    for (int i = tid; i < 8 * P2_HPAD; i += 256) hs[0][i] = 0.f;
    __syncthreads();

    const uint32_t hb[2] = { smem_u32(hs[0]), smem_u32(hs[1]) };
    const uint32_t lm_row = (uint32_t)((lane & 7) * P2_HPAD + (lane >> 3) * 4) * 4;

    float4 A[4][4][2];   // [slot][ks][mt]

    auto ldA = [&](int s, int st) {
        const size_t base = ((size_t)s * 8 + w) * 256 + lane;
#pragma unroll
        for (int ks = 0; ks < 4; ks++)
#pragma unroll
            for (int mt = 0; mt < 2; mt++)
                A[st][ks][mt] = __ldg(&WhP_g[base + (ks * 2 + mt) * 32]);
    };

    ldA(0, 0); ldA(1, 1); ldA(2, 2);

    float acc[2][4];
    float z[2][4];
    int s = 0;

    for (int t = 0; t < S_; t++) {
        const uint32_t hrd = hb[t & 1];          // read buffer (h_{t-1})
        float* hwr = hs[(t & 1) ^ 1];            // write buffer (h_t)

#pragma unroll
        for (int mt = 0; mt < 2; mt++)
#pragma unroll
            for (int i = 0; i < 4; i++) acc[mt][i] = 0.f;

        // Z prefetch (independent of h); consumed at epilogue ~2500 cyc later
#pragma unroll
        for (int mt = 0; mt < 2; mt++) {
            const int col = mb + mt * 16 + grp;
            z[mt][0] = __ldg(&out[((size_t)(brow + n0)     * S_ + t) * DO_ + col]);
            z[mt][1] = __ldg(&out[((size_t)(brow + n0 + 1) * S_ + t) * DO_ + col]);
            z[mt][2] = __ldg(&out[((size_t)(brow + n0)     * S_ + t) * DO_ + col + 8]);
            z[mt][3] = __ldg(&out[((size_t)(brow + n0 + 1) * S_ + t) * DO_ + col + 8]);
        }

#pragma unroll 1
        for (int c = 0; c < 8; c++) {
            // issue next A-chunk load first (slot (s+3)&3 is free: s-1 consumed last iter)
            if (s + 3 < 4 * S_ * 2) { if (s + 3 < S_ * 8) ldA(s + 3, (s + 3) & 3); }

            const uint32_t a0 = hrd + lm_row + (uint32_t)(c * 32) * 4;
            uint32_t b0, b1, b2, b3, b4, b5, b6, b7;
            LDSM_X4(b0, b1, b2, b3, a0);
            LDSM_X4(b4, b5, b6, b7, a0 + 64);
            const uint32_t bb[8] = { b0, b1, b2, b3, b4, b5, b6, b7 };

            const int st = s & 3;
#pragma unroll
            for (int ks = 0; ks < 4; ks++) {
#pragma unroll
                for (int mt = 0; mt < 2; mt++) {
                    const float4 af = A[st][ks][mt];
                    mma_tf32(acc[mt], f2u(af.x), f2u(af.y), f2u(af.z), f2u(af.w),
                             bb[2 * ks], bb[2 * ks + 1]);
                }
            }
            s++;
        }

        // epilogue: h = tanh(Z + Wh^T h); write gmem + other h buffer
#pragma unroll
        for (int mt = 0; mt < 2; mt++) {
            const int col = mb + mt * 16 + grp;
            const float h0 = fast_tanh(z[mt][0] + acc[mt][0]);
            const float h1 = fast_tanh(z[mt][1] + acc[mt][1]);
            const float h2 = fast_tanh(z[mt][2] + acc[mt][2]);
            const float h3 = fast_tanh(z[mt][3] + acc[mt][3]);

            out[((size_t)(brow + n0)     * S_ + t) * DO_ + col]     = h0;
            out[((size_t)(brow + n0 + 1) * S_ + t) * DO_ + col]     = h1;
            out[((size_t)(brow + n0)     * S_ + t) * DO_ + col + 8] = h2;
            out[((size_t)(brow + n0 + 1) * S_ + t) * DO_ + col + 8] = h3;

            hwr[n0 * P2_HPAD + col]           = h0;
            hwr[(n0 + 1) * P2_HPAD + col]     = h1;
            hwr[n0 * P2_HPAD + col + 8]       = h2;
            hwr[(n0 + 1) * P2_HPAD + col + 8] = h3;
        }

        __syncthreads();   // h_t visible before next step's ldmatrix reads
    }
}

// ---------------- launch ----------------

extern "C" void kernel_launch(void* const* d_in, const int* in_sizes, int n_in,
                              void* d_out, int out_size)
{
    const float* x  = (const float*)d_in[0];   // [B, S, DI]
    const float* Wx = (const float*)d_in[1];   // [S, DI, DO]
    const float* Wh = (const float*)d_in[2];   // [S, DO, DO]
    float* out = (float*)d_out;                // [B, S, DO]

    cudaFuncSetAttribute(rnn_phase1, cudaFuncAttributeMaxDynamicSharedMemorySize, P1_SMEM);

    prepack_wh<<<dim3(8, S_), 256>>>(Wh);

    dim3 g1(DO_ / 128, B_ / 128, S_);
    rnn_phase1<<<g1, 256, P1_SMEM>>>(x, Wx, out);

    rnn_phase2<<<B_ / 8, 256>>>(out);
}

// round 7
// speedup vs baseline: 2.8791x; 2.8791x over previous
#include <cuda_runtime.h>
#include <cuda_bf16.h>
#include <math.h>
#include <stdint.h>

#define B_  512
#define S_  512
#define DI_ 256
#define DO_ 256

// Packed Wh A-fragments: [g(=t*8+chunk)][wm(8)][ks(4)][mt(2)][lane(32)], one float4 each.
// 4096 * 8 * 4 * 2 * 32 = 8,388,608 float4 = 134 MB.
__device__ float4 WhP_g[(size_t)S_ * 8 * 8 * 4 * 2 * 32];

// ---------------- helpers ----------------

__device__ __forceinline__ void cpasync16(void* smem_dst, const void* gsrc) {
    unsigned saddr = (unsigned)__cvta_generic_to_shared(smem_dst);
    asm volatile("cp.async.cg.shared.global [%0], [%1], 16;\n" :: "r"(saddr), "l"(gsrc));
}
__device__ __forceinline__ void cp_commit() { asm volatile("cp.async.commit_group;\n"); }
template <int N> __device__ __forceinline__ void cp_wait() {
    asm volatile("cp.async.wait_group %0;\n" :: "n"(N));
}
__device__ __forceinline__ unsigned f2u(float f) { return __float_as_uint(f); }
__device__ __forceinline__ float fast_tanh(float x) {
    float e = __expf(2.0f * x);
    return 1.0f - __fdividef(2.0f, e + 1.0f);
}
__device__ __forceinline__ uint32_t smem_u32(const void* p) {
    return (uint32_t)__cvta_generic_to_shared(p);
}

__device__ __forceinline__ void mma_tf32(float c[4],
                                         unsigned a0, unsigned a1, unsigned a2, unsigned a3,
                                         unsigned b0, unsigned b1) {
    asm volatile(
        "mma.sync.aligned.m16n8k8.row.col.f32.tf32.tf32.f32 "
        "{%0,%1,%2,%3}, {%4,%5,%6,%7}, {%8,%9}, {%0,%1,%2,%3};\n"
        : "+f"(c[0]), "+f"(c[1]), "+f"(c[2]), "+f"(c[3])
        : "r"(a0), "r"(a1), "r"(a2), "r"(a3), "r"(b0), "r"(b1));
}

#define LDSM_X4(r0, r1, r2, r3, addr) \
    asm volatile("ldmatrix.sync.aligned.m8n8.x4.shared.b16 {%0,%1,%2,%3}, [%4];" \
                 : "=r"(r0), "=r"(r1), "=r"(r2), "=r"(r3) : "r"(addr))

// ---------------- Phase 0: pack Wh into fragment-major layout (unchanged) ----------------

__global__ __launch_bounds__(256, 1) void prepack_wh(const float* __restrict__ Wh)
{
    __shared__ float tile[32 * 260];
    const int slab = blockIdx.x;
    const int t    = blockIdx.y;
    const int tid  = threadIdx.x;
    const float* src = Wh + (size_t)t * (DO_ * DO_) + (size_t)slab * 32 * DO_;

#pragma unroll
    for (int j = 0; j < 8; j++) {
        int idx = tid + j * 256;
        int r = idx >> 6, q = idx & 63;
        *(float4*)&tile[r * 260 + q * 4] = *(const float4*)&src[r * DO_ + q * 4];
    }
    __syncthreads();

    const size_t g = (size_t)t * 8 + slab;
#pragma unroll
    for (int j = 0; j < 8; j++) {
        int idx  = tid + j * 256;
        int lane = idx & 31;
        int mt   = (idx >> 5) & 1;
        int ks   = (idx >> 6) & 3;
        int wm   = (idx >> 8) & 7;
        int kloc = ks * 8 + (lane & 3);
        int m0   = wm * 32 + mt * 16 + (lane >> 2);
        float4 v;
        v.x = tile[kloc * 260 + m0];
        v.y = tile[kloc * 260 + m0 + 8];
        v.z = tile[(kloc + 4) * 260 + m0];
        v.w = tile[(kloc + 4) * 260 + m0 + 8];
        WhP_g[(g * 8 + wm) * 256 + (ks * 2 + mt) * 32 + lane] = v;
    }
}

// ---------------- Phase 1: Z[b,t,:] = x[b,t,:] @ Wx[t]  (unchanged, 2 CTAs/SM) ----------------

#define P1_AS  (128 * 36)
#define P1_BS  (32 * 132)
#define P1_SMEM ((2 * P1_AS + 2 * P1_BS) * 4)

__global__ __launch_bounds__(256, 2) void rnn_phase1(
    const float* __restrict__ x, const float* __restrict__ Wx, float* __restrict__ out)
{
    extern __shared__ float sm[];
    float* As[2] = { sm, sm + P1_AS };
    float* Bs[2] = { sm + 2 * P1_AS, sm + 2 * P1_AS + P1_BS };

    const int t      = blockIdx.z;
    const int m_base = blockIdx.y * 128;
    const int n_base = blockIdx.x * 128;
    const int tid    = threadIdx.x;
    const int warp   = tid >> 5, lane = tid & 31;
    const int wm     = warp & 3, wn = warp >> 2;
    const int grp    = lane >> 2, tig = lane & 3;

    float acc[2][8][4];
#pragma unroll
    for (int mt = 0; mt < 2; mt++)
#pragma unroll
        for (int nt = 0; nt < 8; nt++)
#pragma unroll
            for (int i = 0; i < 4; i++) acc[mt][nt][i] = 0.f;

    auto loadA = [&](int kc, int buf) {
#pragma unroll
        for (int j = 0; j < 4; j++) {
            int i = tid + j * 256;
            int r = i >> 3, q = i & 7;
            cpasync16(&As[buf][r * 36 + q * 4],
                      x + ((m_base + r) * S_ + t) * DI_ + kc * 32 + q * 4);
        }
        cp_commit();
    };
    auto loadB = [&](int kc, int buf) {
#pragma unroll
        for (int j = 0; j < 4; j++) {
            int i = tid + j * 256;
            int k = i >> 5, q = i & 31;
            cpasync16(&Bs[buf][k * 132 + q * 4],
                      Wx + t * (DI_ * DO_) + (kc * 32 + k) * DO_ + n_base + q * 4);
        }
        cp_commit();
    };

    loadA(0, 0); loadB(0, 0);
    loadA(1, 1); loadB(1, 1);

    for (int kc = 0; kc < 8; kc++) {
        if (kc < 7) cp_wait<2>(); else cp_wait<0>();
        __syncthreads();
        const int buf = kc & 1;
        const float* A = As[buf];
        const float* Bsm = Bs[buf];
#pragma unroll
        for (int ks = 0; ks < 4; ks++) {
            const int k = ks * 8;
            unsigned a[2][4];
#pragma unroll
            for (int mt = 0; mt < 2; mt++) {
                const int rb = wm * 32 + mt * 16;
                a[mt][0] = f2u(A[(rb + grp)     * 36 + k + tig]);
                a[mt][1] = f2u(A[(rb + grp + 8) * 36 + k + tig]);
                a[mt][2] = f2u(A[(rb + grp)     * 36 + k + 4 + tig]);
                a[mt][3] = f2u(A[(rb + grp + 8) * 36 + k + 4 + tig]);
            }
#pragma unroll
            for (int nt = 0; nt < 8; nt++) {
                const int cb = wn * 64 + nt * 8 + grp;
                unsigned b0 = f2u(Bsm[(k + tig)     * 132 + cb]);
                unsigned b1 = f2u(Bsm[(k + 4 + tig) * 132 + cb]);
#pragma unroll
                for (int mt = 0; mt < 2; mt++)
                    mma_tf32(acc[mt][nt], a[mt][0], a[mt][1], a[mt][2], a[mt][3], b0, b1);
            }
        }
        __syncthreads();
        if (kc + 2 < 8) { loadA(kc + 2, buf); loadB(kc + 2, buf); }
    }

#pragma unroll
    for (int mt = 0; mt < 2; mt++) {
#pragma unroll
        for (int nt = 0; nt < 8; nt++) {
            const int row = m_base + wm * 32 + mt * 16 + grp;
            const int col = n_base + wn * 64 + nt * 8 + 2 * tig;
            const int g0 = (row * S_ + t) * DO_ + col;
            float2 v0; v0.x = acc[mt][nt][0]; v0.y = acc[mt][nt][1];
            *(float2*)&out[g0] = v0;
            const int g1 = ((row + 8) * S_ + t) * DO_ + col;
            float2 v1; v1.x = acc[mt][nt][2]; v1.y = acc[mt][nt][3];
            *(float2*)&out[g1] = v1;
        }
    }
}

// ---------------- Phase 2 v5: 64 CTAs x 256 thr, STATIC-slot register ring ----------------
// h_t^T = tanh(Z_t^T + Wh[t]^T @ h_{t-1}^T). 8 warps; warp w owns m cols [w*32, w*32+32),
// full K=256 = 8 chunks of 32. Chunk loop FULLY UNROLLED: chunk c of every step sits in
// ring slot c&3 (8 % 4 == 0), prefetch distance 3, all slot indices compile-time.
// h double-buffered in smem -> one __syncthreads per step. B-frags via ldmatrix.x4.

#define P2_HPAD 260

__global__ __launch_bounds__(256, 1) void rnn_phase2(float* __restrict__ out)
{
    __shared__ __align__(16) float hs[2][8 * P2_HPAD];

    const int tid  = threadIdx.x;
    const int w    = tid >> 5, lane = tid & 31;
    const int grp  = lane >> 2, tig = lane & 3;
    const int brow = blockIdx.x * 8;
    const int mb   = w * 32;
    const int n0   = 2 * tig;

    for (int i = tid; i < 8 * P2_HPAD; i += 256) hs[0][i] = 0.f;
    __syncthreads();

    const uint32_t hb[2] = { smem_u32(hs[0]), smem_u32(hs[1]) };
    const uint32_t lm_row = (uint32_t)((lane & 7) * P2_HPAD + (lane >> 3) * 4) * 4;

    float4 A[4][4][2];   // ring: [slot][ks][mt] — only ever indexed with constants

    const size_t lane_off = lane;

    auto ldA = [&](int g, int slot) {   // slot must be a compile-time constant at call site
        const size_t base = ((size_t)g * 8 + w) * 256 + lane_off;
#pragma unroll
        for (int ks = 0; ks < 4; ks++)
#pragma unroll
            for (int mt = 0; mt < 2; mt++)
                A[slot][ks][mt] = __ldg(&WhP_g[base + (ks * 2 + mt) * 32]);
    };

    ldA(0, 0); ldA(1, 1); ldA(2, 2);

    float acc[2][4];
    float z[2][4];

    for (int t = 0; t < S_; t++) {
        const uint32_t hrd = hb[t & 1];
        float* hwr = hs[(t & 1) ^ 1];

#pragma unroll
        for (int mt = 0; mt < 2; mt++)
#pragma unroll
            for (int i = 0; i < 4; i++) acc[mt][i] = 0.f;

        // Z prefetch (independent of h)
#pragma unroll
        for (int mt = 0; mt < 2; mt++) {
            const int col = mb + mt * 16 + grp;
            z[mt][0] = __ldg(&out[((size_t)(brow + n0)     * S_ + t) * DO_ + col]);
            z[mt][1] = __ldg(&out[((size_t)(brow + n0 + 1) * S_ + t) * DO_ + col]);
            z[mt][2] = __ldg(&out[((size_t)(brow + n0)     * S_ + t) * DO_ + col + 8]);
            z[mt][3] = __ldg(&out[((size_t)(brow + n0 + 1) * S_ + t) * DO_ + col + 8]);
        }

#pragma unroll
        for (int c = 0; c < 8; c++) {
            // B-frags for this chunk
            const uint32_t a0 = hrd + lm_row + (uint32_t)(c * 32) * 4;
            uint32_t b0, b1, b2, b3, b4, b5, b6, b7;
            LDSM_X4(b0, b1, b2, b3, a0);
            LDSM_X4(b4, b5, b6, b7, a0 + 64);

            // consume ring slot c&3 (static)
#pragma unroll
            for (int mt = 0; mt < 2; mt++) {
                {
                    const float4 af = A[c & 3][0][mt];
                    mma_tf32(acc[mt], f2u(af.x), f2u(af.y), f2u(af.z), f2u(af.w), b0, b1);
                }
                {
                    const float4 af = A[c & 3][1][mt];
                    mma_tf32(acc[mt], f2u(af.x), f2u(af.y), f2u(af.z), f2u(af.w), b2, b3);
                }
                {
                    const float4 af = A[c & 3][2][mt];
                    mma_tf32(acc[mt], f2u(af.x), f2u(af.y), f2u(af.z), f2u(af.w), b4, b5);
                }
                {
                    const float4 af = A[c & 3][3][mt];
                    mma_tf32(acc[mt], f2u(af.x), f2u(af.y), f2u(af.z), f2u(af.w), b6, b7);
                }
            }

            // prefetch chunk 8t+c+3 into slot (c+3)&3 (static); after-consume keeps WAR clean
            {
                const int gp = t * 8 + c + 3;
                if (gp < S_ * 8) ldA(gp, (c + 3) & 3);
            }
        }

        // epilogue: h = tanh(Z + Wh^T h)
#pragma unroll
        for (int mt = 0; mt < 2; mt++) {
            const int col = mb + mt * 16 + grp;
            const float h0 = fast_tanh(z[mt][0] + acc[mt][0]);
            const float h1 = fast_tanh(z[mt][1] + acc[mt][1]);
            const float h2 = fast_tanh(z[mt][2] + acc[mt][2]);
            const float h3 = fast_tanh(z[mt][3] + acc[mt][3]);

            out[((size_t)(brow + n0)     * S_ + t) * DO_ + col]     = h0;
            out[((size_t)(brow + n0 + 1) * S_ + t) * DO_ + col]     = h1;
            out[((size_t)(brow + n0)     * S_ + t) * DO_ + col + 8] = h2;
            out[((size_t)(brow + n0 + 1) * S_ + t) * DO_ + col + 8] = h3;

            hwr[n0 * P2_HPAD + col]           = h0;
            hwr[(n0 + 1) * P2_HPAD + col]     = h1;
            hwr[n0 * P2_HPAD + col + 8]       = h2;
            hwr[(n0 + 1) * P2_HPAD + col + 8] = h3;
        }

        __syncthreads();   // h_t visible before next step's ldmatrix reads
    }
}

// ---------------- launch ----------------

extern "C" void kernel_launch(void* const* d_in, const int* in_sizes, int n_in,
                              void* d_out, int out_size)
{
    const float* x  = (const float*)d_in[0];   // [B, S, DI]
    const float* Wx = (const float*)d_in[1];   // [S, DI, DO]
    const float* Wh = (const float*)d_in[2];   // [S, DO, DO]
    float* out = (float*)d_out;                // [B, S, DO]

    cudaFuncSetAttribute(rnn_phase1, cudaFuncAttributeMaxDynamicSharedMemorySize, P1_SMEM);

    prepack_wh<<<dim3(8, S_), 256>>>(Wh);

    dim3 g1(DO_ / 128, B_ / 128, S_);
    rnn_phase1<<<g1, 256, P1_SMEM>>>(x, Wx, out);

    rnn_phase2<<<B_ / 8, 256>>>(out);
}